// round 16
// baseline (speedup 1.0000x reference)
#include <cuda_runtime.h>
#include <cuda_bf16.h>
#include <cuda_fp16.h>
#include <stdint.h>
#include <math.h>

#define Nn 30000
#define Ee 480000
#define Hh 256
#define Tt 4
#define Gg 64
#define Cc 10
#define STEPS 5
#define BN_EPS 1e-5f

#define WH_COLS (Tt * Hh)      // 1024

// ---------------- scratch (device globals; no runtime allocation) ----------------
__device__ float g_hA[Nn * Hh];
__device__ float g_hB[Nn * Hh];
__device__ float  g_Whf[Nn * WH_COLS];   // fp32 message matrix (steps 0,3,4)
__device__ __half g_Wh16[Nn * WH_COLS];  // fp16 message matrix (steps 1,2; L2-resident)
__device__ float g_grz[Nn * 512];
__device__ float g_gin[Nn * Hh];
__device__ float g_h2[Nn * Hh];
__device__ float g_gate[Nn];
__device__ float g_alpha[Nn];
__device__ float g_hg[Gg * Hh];
__device__ float g_colsum[Hh];
__device__ float g_colsq[Hh];
__device__ float g_scale[Hh];
__device__ float g_shift[Hh];
__device__ float g_bias_rz[512];
__device__ int   g_cnt[Nn];
__device__ int   g_rowptr[Nn + 1];
__device__ int   g_cursor[Nn];
__device__ int   g_eoff[Ee];
__device__ int   g_gcnt[Gg];
__device__ int   g_gstart[Gg + 1];
// bf16 hi/lo split operands for tensor-core GEMMs
__device__ __nv_bfloat16 g_hA_hi[Nn * Hh];
__device__ __nv_bfloat16 g_hA_lo[Nn * Hh];
__device__ __nv_bfloat16 g_hB_hi[Nn * Hh];
__device__ __nv_bfloat16 g_hB_lo[Nn * Hh];
__device__ __nv_bfloat16 g_a_hi[Nn * Hh];
__device__ __nv_bfloat16 g_a_lo[Nn * Hh];
__device__ __nv_bfloat16 g_Wm_hi[WH_COLS * Hh];
__device__ __nv_bfloat16 g_Wm_lo[WH_COLS * Hh];
__device__ __nv_bfloat16 g_wrz_hi[512 * 512];   // [512 out rows][K=512: w_ih | w_hh]
__device__ __nv_bfloat16 g_wrz_lo[512 * 512];
__device__ __nv_bfloat16 g_win_hi[Hh * Hh];     // w_ih rows 512:768
__device__ __nv_bfloat16 g_win_lo[Hh * Hh];
__device__ __nv_bfloat16 g_whn_hi[Hh * Hh];     // w_hh rows 512:768
__device__ __nv_bfloat16 g_whn_lo[Hh * Hh];

// ---------------- ptx helpers (baseline ISA) ----------------
__device__ __forceinline__ uint32_t smem_u32(const void* p) {
    uint32_t a;
    asm("{ .reg .u64 t; cvta.to.shared.u64 t, %1; cvt.u32.u64 %0, t; }" : "=r"(a) : "l"(p));
    return a;
}
__device__ __forceinline__ void ldm_x4(uint32_t& r0, uint32_t& r1, uint32_t& r2, uint32_t& r3,
                                       uint32_t addr) {
    asm volatile("ldmatrix.sync.aligned.m8n8.x4.shared.b16 {%0,%1,%2,%3}, [%4];"
                 : "=r"(r0), "=r"(r1), "=r"(r2), "=r"(r3) : "r"(addr));
}
__device__ __forceinline__ void mma_bf16(float* d, const uint32_t* a, const uint32_t* b) {
    asm volatile(
        "mma.sync.aligned.m16n8k16.row.col.f32.bf16.bf16.f32 "
        "{%0,%1,%2,%3}, {%4,%5,%6,%7}, {%8,%9}, {%0,%1,%2,%3};"
        : "+f"(d[0]), "+f"(d[1]), "+f"(d[2]), "+f"(d[3])
        : "r"(a[0]), "r"(a[1]), "r"(a[2]), "r"(a[3]), "r"(b[0]), "r"(b[1]));
}
__device__ __forceinline__ void cp16(uint32_t saddr, const void* gaddr) {
    asm volatile("cp.async.cg.shared.global [%0], [%1], 16;" :: "r"(saddr), "l"(gaddr));
}
#define CP_COMMIT() asm volatile("cp.async.commit_group;")
#define CP_WAIT1()  asm volatile("cp.async.wait_group 1;")

// ---------------- persistent tile-looped tensor-core GEMM ------------
// C[M,Ncols] = (A||A2)[M,Kloop] @ (Bhi+Blo)[Ncols,Kloop]^T  (+ epilogue)
// A row stride always 256. K chunks >= kSplit read A2 at k-kSplit.
// fp32 emulation: C = Ahi*Bhi + Ahi*Blo + Alo*Bhi
// BM=128, BN=64, BK=32, 8 warps (4x2), warp tile 32x32, 2 smem stages.
// Each CTA grid-strides over linear tile ids (ty*ntx + tx) to avoid wave quantization.
// MODE 0: C(fp32)=acc+bias.  MODE 1: fused GRU epilogue.  MODE 2: Ch(fp16)=acc+bias.
#define SSTR 40  // smem row stride in bf16 elems (80 B, 16B-aligned for ldmatrix)
#define OFF_ALO 10240
#define OFF_BHI 20480
#define OFF_BLO 25600
#define STAGE_BYTES 30720
#define GEMM_SMEM (2 * STAGE_BYTES)

template <int MODE>
__global__ __launch_bounds__(256) void gemm_mma(
    const __nv_bfloat16* __restrict__ Ahi, const __nv_bfloat16* __restrict__ Alo,
    const __nv_bfloat16* __restrict__ A2hi, const __nv_bfloat16* __restrict__ A2lo,
    const __nv_bfloat16* __restrict__ Bhi, const __nv_bfloat16* __restrict__ Blo,
    const float* __restrict__ bias, float* __restrict__ C, __half* __restrict__ Ch,
    const float* __restrict__ grz, const float* __restrict__ gin,
    const float* __restrict__ hold, float* __restrict__ hnew,
    __nv_bfloat16* __restrict__ hnhi, __nv_bfloat16* __restrict__ hnlo,
    int M, int Ncols, int Kloop, int kSplit, int ldb, int ntiles, int ntx) {
    extern __shared__ char smem[];
    const uint32_t sbase = smem_u32(smem);

    const int tid = threadIdx.x;
    const int warp = tid >> 5;
    const int lane = tid & 31;
    const int wm = warp >> 1;
    const int wn = warp & 1;

    // tile-independent per-thread constants
    const int grow = tid >> 2;
    const int gk4 = (tid & 3) * 8;
    const uint32_t sA0 = (uint32_t)((grow * SSTR + gk4) * 2);
    const uint32_t sA1 = (uint32_t)(((grow + 64) * SSTR + gk4) * 2);
    const uint32_t sB0 = (uint32_t)((grow * SSTR + gk4) * 2);

    const int alr = lane & 15, alh = lane >> 4;
    uint32_t aoff[2];
#pragma unroll
    for (int tm = 0; tm < 2; tm++)
        aoff[tm] = (uint32_t)((wm * 32 + tm * 16 + alr) * (SSTR * 2) + alh * 16);
    const int bnr = (lane & 7) + ((lane >> 4) & 1) * 8;
    const int bkh = ((lane >> 3) & 1) * 16;
    uint32_t boff[2];
#pragma unroll
    for (int bt = 0; bt < 2; bt++)
        boff[bt] = (uint32_t)((wn * 32 + bt * 16 + bnr) * (SSTR * 2) + bkh);

    const int niter = Kloop >> 5;
    const int erow = (lane >> 2);
    const int ecol = (lane & 3) * 2;

    for (int tile = blockIdx.x; tile < ntiles; tile += gridDim.x) {
        const int ty = tile / ntx;
        const int tx = tile - ty * ntx;
        const int m0 = ty * 128;
        const int n0 = tx * 64;

        const int arow0 = min(m0 + grow, M - 1);   // clamp (row m affects only C row m)
        const int arow1 = min(m0 + grow + 64, M - 1);
        const int brow = n0 + grow;

        float acc[2][4][4];
#pragma unroll
        for (int i = 0; i < 2; i++)
#pragma unroll
            for (int j = 0; j < 4; j++)
#pragma unroll
                for (int q = 0; q < 4; q++) acc[i][j][q] = 0.0f;

#define ISSUE_LOADS(K0, S)                                                             \
    do {                                                                               \
        uint32_t b_ = sbase + (S) * STAGE_BYTES;                                       \
        const bool sec_ = (K0) >= kSplit;                                              \
        const __nv_bfloat16* pAhi_ = sec_ ? A2hi : Ahi;                                \
        const __nv_bfloat16* pAlo_ = sec_ ? A2lo : Alo;                                \
        const int ko_ = sec_ ? (K0) - kSplit : (K0);                                   \
        cp16(b_ + sA0, pAhi_ + (size_t)arow0 * 256 + ko_ + gk4);                       \
        cp16(b_ + sA1, pAhi_ + (size_t)arow1 * 256 + ko_ + gk4);                       \
        cp16(b_ + OFF_ALO + sA0, pAlo_ + (size_t)arow0 * 256 + ko_ + gk4);             \
        cp16(b_ + OFF_ALO + sA1, pAlo_ + (size_t)arow1 * 256 + ko_ + gk4);             \
        cp16(b_ + OFF_BHI + sB0, Bhi + (size_t)brow * ldb + (K0) + gk4);               \
        cp16(b_ + OFF_BLO + sB0, Blo + (size_t)brow * ldb + (K0) + gk4);               \
    } while (0)

        ISSUE_LOADS(0, 0);
        CP_COMMIT();

        for (int it = 0; it < niter; it++) {
            if (it + 1 < niter) ISSUE_LOADS((it + 1) * 32, (it + 1) & 1);
            CP_COMMIT();
            CP_WAIT1();
            __syncthreads();

            const uint32_t stg = sbase + (it & 1) * STAGE_BYTES;
#pragma unroll
            for (int kk = 0; kk < 2; kk++) {
                uint32_t ah[2][4], al[2][4], bh[2][4], bl[2][4];
#pragma unroll
                for (int tm = 0; tm < 2; tm++) {
                    ldm_x4(ah[tm][0], ah[tm][1], ah[tm][2], ah[tm][3], stg + aoff[tm] + kk * 32);
                    ldm_x4(al[tm][0], al[tm][1], al[tm][2], al[tm][3], stg + OFF_ALO + aoff[tm] + kk * 32);
                }
#pragma unroll
                for (int bt = 0; bt < 2; bt++) {
                    ldm_x4(bh[bt][0], bh[bt][1], bh[bt][2], bh[bt][3], stg + OFF_BHI + boff[bt] + kk * 32);
                    ldm_x4(bl[bt][0], bl[bt][1], bl[bt][2], bl[bt][3], stg + OFF_BLO + boff[bt] + kk * 32);
                }
#pragma unroll
                for (int tm = 0; tm < 2; tm++) {
#pragma unroll
                    for (int tn = 0; tn < 4; tn++) {
                        const uint32_t* bph = &bh[tn >> 1][(tn & 1) * 2];
                        const uint32_t* bpl = &bl[tn >> 1][(tn & 1) * 2];
                        mma_bf16(acc[tm][tn], ah[tm], bph);
                        mma_bf16(acc[tm][tn], ah[tm], bpl);
                        mma_bf16(acc[tm][tn], al[tm], bph);
                    }
                }
            }
            __syncthreads();   // also fences smem reads before next tile's cp.async writes
        }

        // epilogue
#pragma unroll
        for (int tm = 0; tm < 2; tm++) {
#pragma unroll
            for (int tn = 0; tn < 4; tn++) {
                int col = n0 + wn * 32 + tn * 8 + ecol;
                float2 bv = *(const float2*)&bias[col];
#pragma unroll
                for (int half = 0; half < 2; half++) {
                    int r = m0 + wm * 32 + tm * 16 + erow + half * 8;
                    if (r >= M) continue;
                    float vx = acc[tm][tn][half * 2 + 0] + bv.x;
                    float vy = acc[tm][tn][half * 2 + 1] + bv.y;
                    if (MODE == 0) {
                        float2 o;
                        o.x = vx;
                        o.y = vy;
                        *(float2*)&C[(size_t)r * Ncols + col] = o;
                    } else if (MODE == 2) {
                        __half2 o;
                        o.x = __float2half(vx);
                        o.y = __float2half(vy);
                        *(__half2*)&Ch[(size_t)r * Ncols + col] = o;
                    } else {
                        float2 rz_r = *(const float2*)&grz[(size_t)r * 512 + col];
                        float2 rz_z = *(const float2*)&grz[(size_t)r * 512 + 256 + col];
                        float2 gn = *(const float2*)&gin[(size_t)r * 256 + col];
                        float2 ho = *(const float2*)&hold[(size_t)r * 256 + col];
                        float rr0 = 1.0f / (1.0f + expf(-rz_r.x));
                        float rr1 = 1.0f / (1.0f + expf(-rz_r.y));
                        float zz0 = 1.0f / (1.0f + expf(-rz_z.x));
                        float zz1 = 1.0f / (1.0f + expf(-rz_z.y));
                        float nn0 = tanhf(gn.x + rr0 * vx);
                        float nn1 = tanhf(gn.y + rr1 * vy);
                        float o0 = (1.0f - zz0) * nn0 + zz0 * ho.x;
                        float o1 = (1.0f - zz1) * nn1 + zz1 * ho.y;
                        float2 ov;
                        ov.x = o0;
                        ov.y = o1;
                        *(float2*)&hnew[(size_t)r * 256 + col] = ov;
                        __nv_bfloat16 h0 = __float2bfloat16(o0);
                        __nv_bfloat16 h1 = __float2bfloat16(o1);
                        __nv_bfloat162 hv, lv;
                        hv.x = h0;
                        hv.y = h1;
                        lv.x = __float2bfloat16(o0 - __bfloat162float(h0));
                        lv.y = __float2bfloat16(o1 - __bfloat162float(h1));
                        *(__nv_bfloat162*)&hnhi[(size_t)r * 256 + col] = hv;
                        *(__nv_bfloat162*)&hnlo[(size_t)r * 256 + col] = lv;
                    }
                }
            }
        }
    }
}

// ---------------- weight prep ----------------
__global__ void split_k(const float* __restrict__ x, __nv_bfloat16* __restrict__ hi,
                        __nv_bfloat16* __restrict__ lo, int n) {
    int i = blockIdx.x * blockDim.x + threadIdx.x;
    if (i < n) {
        float v = x[i];
        __nv_bfloat16 h = __float2bfloat16(v);
        hi[i] = h;
        lo[i] = __float2bfloat16(v - __bfloat162float(h));
    }
}
__global__ void prep_rz_k(const float* __restrict__ wih, const float* __restrict__ whh,
                          const float* __restrict__ bih, const float* __restrict__ bhh,
                          __nv_bfloat16* __restrict__ hi, __nv_bfloat16* __restrict__ lo,
                          float* __restrict__ brz) {
    int i = blockIdx.x * blockDim.x + threadIdx.x;
    if (i >= 512 * 512) return;
    int j = i >> 9;
    int k = i & 511;
    float v = (k < 256) ? wih[j * 256 + k] : whh[j * 256 + (k - 256)];
    __nv_bfloat16 h = __float2bfloat16(v);
    hi[i] = h;
    lo[i] = __float2bfloat16(v - __bfloat162float(h));
    if (i < 512) brz[i] = bih[i] + bhh[i];
}
__global__ void prep_n_k(const float* __restrict__ w, __nv_bfloat16* __restrict__ hi,
                         __nv_bfloat16* __restrict__ lo) {
    int i = blockIdx.x * blockDim.x + threadIdx.x;
    if (i >= 256 * 256) return;
    float v = w[512 * 256 + i];
    __nv_bfloat16 h = __float2bfloat16(v);
    hi[i] = h;
    lo[i] = __float2bfloat16(v - __bfloat162float(h));
}
__global__ void init_h_k(const float* __restrict__ feat, float* __restrict__ h,
                         __nv_bfloat16* __restrict__ hhi, __nv_bfloat16* __restrict__ hlo) {
    int i = blockIdx.x * blockDim.x + threadIdx.x;
    if (i < Nn * Hh) {
        float v = feat[i];
        h[i] = v;
        __nv_bfloat16 hb = __float2bfloat16(v);
        hhi[i] = hb;
        hlo[i] = __float2bfloat16(v - __bfloat162float(hb));
    }
}

// ---------------- CSR construction ----------------
__global__ void zero_f(float* p, int n) {
    int i = blockIdx.x * blockDim.x + threadIdx.x;
    if (i < n) p[i] = 0.0f;
}
__global__ void zero_i(int* p, int n) {
    int i = blockIdx.x * blockDim.x + threadIdx.x;
    if (i < n) p[i] = 0;
}
__global__ void hist_k(const int* __restrict__ dst, int* cnt) {
    int e = blockIdx.x * blockDim.x + threadIdx.x;
    if (e < Ee) atomicAdd(&cnt[dst[e]], 1);
}
__global__ void scan_k(const int* __restrict__ cnt, int* rowptr) {
    __shared__ int partial[1024];
    const int CH = (Nn + 1023) / 1024;
    int tid = threadIdx.x;
    int base = tid * CH;
    int s = 0;
#pragma unroll
    for (int i = 0; i < CH; i++) {
        int idx = base + i;
        if (idx < Nn) s += cnt[idx];
    }
    partial[tid] = s;
    __syncthreads();
    for (int off = 1; off < 1024; off <<= 1) {
        int v = (tid >= off) ? partial[tid - off] : 0;
        __syncthreads();
        partial[tid] += v;
        __syncthreads();
    }
    int run = partial[tid] - s;
    for (int i = 0; i < CH; i++) {
        int idx = base + i;
        if (idx < Nn) { rowptr[idx] = run; run += cnt[idx]; }
    }
    if (tid == 1023) rowptr[Nn] = partial[1023];
}
__global__ void copy_rowptr_k(const int* __restrict__ rowptr, int* cursor) {
    int i = blockIdx.x * blockDim.x + threadIdx.x;
    if (i < Nn) cursor[i] = rowptr[i];
}
__global__ void scatter_k(const int* __restrict__ src, const int* __restrict__ dst,
                          const int* __restrict__ etype, int* cursor, int* eoff) {
    int e = blockIdx.x * blockDim.x + threadIdx.x;
    if (e < Ee) {
        int pos = atomicAdd(&cursor[dst[e]], 1);
        eoff[pos] = src[e] * WH_COLS + etype[e] * Hh;
    }
}

// ---------------- edge aggregation (fp32 Wh) ----------------
__global__ void aggregate_f_k(const float* __restrict__ Wh, const int* __restrict__ rowptr,
                              const int* __restrict__ eoff,
                              __nv_bfloat16* __restrict__ ahi, __nv_bfloat16* __restrict__ alo) {
    int d = blockIdx.x;
    int lane = threadIdx.x;  // 64 threads, 4 floats each
    int s = rowptr[d];
    int e = rowptr[d + 1];
    float4 acc0 = make_float4(0.f, 0.f, 0.f, 0.f);
    float4 acc1 = make_float4(0.f, 0.f, 0.f, 0.f);
    int i = s;
    for (; i + 1 < e; i += 2) {
        int o0 = __ldg(&eoff[i]);
        int o1 = __ldg(&eoff[i + 1]);
        float4 v0 = __ldg((const float4*)&Wh[o0] + lane);
        float4 v1 = __ldg((const float4*)&Wh[o1] + lane);
        acc0.x += v0.x; acc0.y += v0.y; acc0.z += v0.z; acc0.w += v0.w;
        acc1.x += v1.x; acc1.y += v1.y; acc1.z += v1.z; acc1.w += v1.w;
    }
    if (i < e) {
        int o0 = __ldg(&eoff[i]);
        float4 v0 = __ldg((const float4*)&Wh[o0] + lane);
        acc0.x += v0.x; acc0.y += v0.y; acc0.z += v0.z; acc0.w += v0.w;
    }
    float vals[4] = {acc0.x + acc1.x, acc0.y + acc1.y, acc0.z + acc1.z, acc0.w + acc1.w};
    __nv_bfloat16 hb[4], lb[4];
#pragma unroll
    for (int q = 0; q < 4; q++) {
        hb[q] = __float2bfloat16(vals[q]);
        lb[q] = __float2bfloat16(vals[q] - __bfloat162float(hb[q]));
    }
    *(uint2*)&ahi[(size_t)d * Hh + lane * 4] = *(uint2*)hb;
    *(uint2*)&alo[(size_t)d * Hh + lane * 4] = *(uint2*)lb;
}

// ---------------- edge aggregation (fp16 Wh, L2-resident): fp32 accumulation ----------------
__global__ void aggregate_h_k(const __half* __restrict__ Wh, const int* __restrict__ rowptr,
                              const int* __restrict__ eoff,
                              __nv_bfloat16* __restrict__ ahi, __nv_bfloat16* __restrict__ alo) {
    int d = blockIdx.x;
    int lane = threadIdx.x;  // 64 threads, 4 halves each
    int s = rowptr[d];
    int e = rowptr[d + 1];
    float4 acc0 = make_float4(0.f, 0.f, 0.f, 0.f);
    float4 acc1 = make_float4(0.f, 0.f, 0.f, 0.f);
    int i = s;
    for (; i + 1 < e; i += 2) {
        int o0 = __ldg(&eoff[i]);
        int o1 = __ldg(&eoff[i + 1]);
        uint2 u0 = __ldg((const uint2*)&Wh[o0] + lane);
        uint2 u1 = __ldg((const uint2*)&Wh[o1] + lane);
        float2 f00 = __half22float2(*(__half2*)&u0.x);
        float2 f01 = __half22float2(*(__half2*)&u0.y);
        float2 f10 = __half22float2(*(__half2*)&u1.x);
        float2 f11 = __half22float2(*(__half2*)&u1.y);
        acc0.x += f00.x; acc0.y += f00.y; acc0.z += f01.x; acc0.w += f01.y;
        acc1.x += f10.x; acc1.y += f10.y; acc1.z += f11.x; acc1.w += f11.y;
    }
    if (i < e) {
        int o0 = __ldg(&eoff[i]);
        uint2 u0 = __ldg((const uint2*)&Wh[o0] + lane);
        float2 f00 = __half22float2(*(__half2*)&u0.x);
        float2 f01 = __half22float2(*(__half2*)&u0.y);
        acc0.x += f00.x; acc0.y += f00.y; acc0.z += f01.x; acc0.w += f01.y;
    }
    float vals[4] = {acc0.x + acc1.x, acc0.y + acc1.y, acc0.z + acc1.z, acc0.w + acc1.w};
    __nv_bfloat16 hb[4], lb[4];
#pragma unroll
    for (int q = 0; q < 4; q++) {
        hb[q] = __float2bfloat16(vals[q]);
        lb[q] = __float2bfloat16(vals[q] - __bfloat162float(hb[q]));
    }
    *(uint2*)&ahi[(size_t)d * Hh + lane * 4] = *(uint2*)hb;
    *(uint2*)&alo[(size_t)d * Hh + lane * 4] = *(uint2*)lb;
}

// ---------------- ELU + batchnorm stats ----------------
__global__ void elu_stats_k(const float* __restrict__ h, float* __restrict__ h2,
                            float* colsum, float* colsq) {
    int c = threadIdx.x;
    int rows_per_block = (Nn + gridDim.x - 1) / gridDim.x;
    int r0 = blockIdx.x * rows_per_block;
    int r1 = min(Nn, r0 + rows_per_block);
    float s = 0.f, q = 0.f;
    for (int r = r0; r < r1; r++) {
        float x = h[(size_t)r * Hh + c];
        float e = x > 0.f ? x : expm1f(x);
        h2[(size_t)r * Hh + c] = e;
        s += e;
        q += e * e;
    }
    atomicAdd(&colsum[c], s);
    atomicAdd(&colsq[c], q);
}
__global__ void bn_final_k(const float* __restrict__ colsum, const float* __restrict__ colsq,
                           const float* __restrict__ gamma, const float* __restrict__ beta,
                           float* scale, float* shift) {
    int c = threadIdx.x;
    float mu = colsum[c] * (1.0f / Nn);
    float var = colsq[c] * (1.0f / Nn) - mu * mu;
    float k = rsqrtf(var + BN_EPS) * gamma[c];
    scale[c] = k;
    shift[c] = beta[c] - mu * k;
}
__global__ void bn_gate_k(float* __restrict__ h2, const float* __restrict__ scale,
                          const float* __restrict__ shift, const float* __restrict__ gw,
                          const float* __restrict__ gb, float* __restrict__ gate) {
    int n = blockIdx.x * 8 + (threadIdx.x >> 5);
    int lane = threadIdx.x & 31;
    if (n >= Nn) return;
    float s = 0.f;
#pragma unroll
    for (int j = 0; j < 8; j++) {
        int c = lane + j * 32;
        float v = h2[(size_t)n * Hh + c] * scale[c] + shift[c];
        h2[(size_t)n * Hh + c] = v;
        s += v * gw[c];
    }
#pragma unroll
    for (int o = 16; o > 0; o >>= 1) s += __shfl_xor_sync(0xffffffffu, s, o);
    if (lane == 0) gate[n] = s + gb[0];
}

// ---------------- per-graph ranges + pooling + classifier ----------------
__global__ void ghist_k(const int* __restrict__ n2g, int* gcnt) {
    int i = blockIdx.x * blockDim.x + threadIdx.x;
    if (i < Nn) atomicAdd(&gcnt[n2g[i]], 1);
}
__global__ void gscan_k(const int* __restrict__ gcnt, int* gstart) {
    if (threadIdx.x == 0 && blockIdx.x == 0) {
        int r = 0;
        for (int g = 0; g < Gg; g++) { gstart[g] = r; r += gcnt[g]; }
        gstart[Gg] = r;
    }
}
__global__ void pool_k(const float* __restrict__ h2, const float* __restrict__ gate,
                       const int* __restrict__ gstart, float* __restrict__ alpha,
                       float* __restrict__ hg) {
    int g = blockIdx.x;
    int t = threadIdx.x;
    __shared__ float red[256];
    int s = gstart[g];
    int e = gstart[g + 1];
    if (e == s) { hg[g * Hh + t] = 0.0f; return; }
    float mx = -3.402823e38f;
    for (int n = s + t; n < e; n += 256) mx = fmaxf(mx, gate[n]);
    red[t] = mx;
    __syncthreads();
    for (int o = 128; o > 0; o >>= 1) {
        if (t < o) red[t] = fmaxf(red[t], red[t + o]);
        __syncthreads();
    }
    mx = red[0];
    __syncthreads();
    float sm = 0.f;
    for (int n = s + t; n < e; n += 256) {
        float ee = expf(gate[n] - mx);
        alpha[n] = ee;
        sm += ee;
    }
    red[t] = sm;
    __syncthreads();
    for (int o = 128; o > 0; o >>= 1) {
        if (t < o) red[t] += red[t + o];
        __syncthreads();
    }
    float inv = 1.0f / red[0];
    __syncthreads();
    float acc0 = 0.f, acc1 = 0.f, acc2 = 0.f, acc3 = 0.f;
    int n = s;
    for (; n + 3 < e; n += 4) {
        acc0 += alpha[n + 0] * h2[(size_t)(n + 0) * Hh + t];
        acc1 += alpha[n + 1] * h2[(size_t)(n + 1) * Hh + t];
        acc2 += alpha[n + 2] * h2[(size_t)(n + 2) * Hh + t];
        acc3 += alpha[n + 3] * h2[(size_t)(n + 3) * Hh + t];
    }
    for (; n < e; n++) acc0 += alpha[n] * h2[(size_t)n * Hh + t];
    hg[g * Hh + t] = (acc0 + acc1 + acc2 + acc3) * inv;
}
__global__ void mlp_k(const float* __restrict__ hg, const float* __restrict__ W1,
                      const float* __restrict__ b1, const float* __restrict__ W2,
                      const float* __restrict__ b2, float* __restrict__ out) {
    int g = blockIdx.x;
    int t = threadIdx.x;
    __shared__ float sh[256];
    __shared__ float sx[128];
    sh[t] = hg[g * Hh + t];
    sh[t + 128] = hg[g * Hh + t + 128];
    __syncthreads();
    float s = b1[t];
#pragma unroll 8
    for (int j = 0; j < 256; j++) s += sh[j] * W1[t * 256 + j];
    sx[t] = fmaxf(s, 0.f);
    __syncthreads();
    if (t < Cc) {
        float o = b2[t];
#pragma unroll 8
        for (int j = 0; j < 128; j++) o += sx[j] * W2[t * 128 + j];
        out[g * Cc + t] = o;
    }
}

// ---------------- launcher ----------------
extern "C" void kernel_launch(void* const* d_in, const int* in_sizes, int n_in,
                              void* d_out, int out_size) {
    const float* feat   = (const float*)d_in[0];
    const int*   src    = (const int*)d_in[1];
    const int*   dst    = (const int*)d_in[2];
    const int*   etype  = (const int*)d_in[3];
    const int*   n2g    = (const int*)d_in[4];
    const float* W_msg  = (const float*)d_in[5];
    const float* b_msg  = (const float*)d_in[6];
    const float* w_ih   = (const float*)d_in[7];
    const float* w_hh   = (const float*)d_in[8];
    const float* b_ih   = (const float*)d_in[9];
    const float* b_hh   = (const float*)d_in[10];
    const float* bn_g   = (const float*)d_in[11];
    const float* bn_b   = (const float*)d_in[12];
    const float* gate_w = (const float*)d_in[13];
    const float* gate_b = (const float*)d_in[14];
    const float* W1     = (const float*)d_in[15];
    const float* b1     = (const float*)d_in[16];
    const float* W2     = (const float*)d_in[17];
    const float* b2     = (const float*)d_in[18];
    float* out = (float*)d_out;

    float *hA, *hB, *Whf, *grz, *gin, *h2, *gate, *alpha, *hg, *colsum, *colsq, *scale, *shift, *brz;
    __half* Wh16;
    int *cnt, *rowptr, *cursor, *eoff, *gcnt, *gstart;
    __nv_bfloat16 *hA_hi, *hA_lo, *hB_hi, *hB_lo, *a_hi, *a_lo;
    __nv_bfloat16 *Wm_hi, *Wm_lo, *wrz_hi, *wrz_lo, *win_hi, *win_lo, *whn_hi, *whn_lo;
    cudaGetSymbolAddress((void**)&hA, g_hA);
    cudaGetSymbolAddress((void**)&hB, g_hB);
    cudaGetSymbolAddress((void**)&Whf, g_Whf);
    cudaGetSymbolAddress((void**)&Wh16, g_Wh16);
    cudaGetSymbolAddress((void**)&grz, g_grz);
    cudaGetSymbolAddress((void**)&gin, g_gin);
    cudaGetSymbolAddress((void**)&h2, g_h2);
    cudaGetSymbolAddress((void**)&gate, g_gate);
    cudaGetSymbolAddress((void**)&alpha, g_alpha);
    cudaGetSymbolAddress((void**)&hg, g_hg);
    cudaGetSymbolAddress((void**)&colsum, g_colsum);
    cudaGetSymbolAddress((void**)&colsq, g_colsq);
    cudaGetSymbolAddress((void**)&scale, g_scale);
    cudaGetSymbolAddress((void**)&shift, g_shift);
    cudaGetSymbolAddress((void**)&brz, g_bias_rz);
    cudaGetSymbolAddress((void**)&cnt, g_cnt);
    cudaGetSymbolAddress((void**)&rowptr, g_rowptr);
    cudaGetSymbolAddress((void**)&cursor, g_cursor);
    cudaGetSymbolAddress((void**)&eoff, g_eoff);
    cudaGetSymbolAddress((void**)&gcnt, g_gcnt);
    cudaGetSymbolAddress((void**)&gstart, g_gstart);
    cudaGetSymbolAddress((void**)&hA_hi, g_hA_hi);
    cudaGetSymbolAddress((void**)&hA_lo, g_hA_lo);
    cudaGetSymbolAddress((void**)&hB_hi, g_hB_hi);
    cudaGetSymbolAddress((void**)&hB_lo, g_hB_lo);
    cudaGetSymbolAddress((void**)&a_hi, g_a_hi);
    cudaGetSymbolAddress((void**)&a_lo, g_a_lo);
    cudaGetSymbolAddress((void**)&Wm_hi, g_Wm_hi);
    cudaGetSymbolAddress((void**)&Wm_lo, g_Wm_lo);
    cudaGetSymbolAddress((void**)&wrz_hi, g_wrz_hi);
    cudaGetSymbolAddress((void**)&wrz_lo, g_wrz_lo);
    cudaGetSymbolAddress((void**)&win_hi, g_win_hi);
    cudaGetSymbolAddress((void**)&win_lo, g_win_lo);
    cudaGetSymbolAddress((void**)&whn_hi, g_whn_hi);
    cudaGetSymbolAddress((void**)&whn_lo, g_whn_lo);

    cudaFuncSetAttribute(gemm_mma<0>, cudaFuncAttributeMaxDynamicSharedMemorySize, GEMM_SMEM);
    cudaFuncSetAttribute(gemm_mma<1>, cudaFuncAttributeMaxDynamicSharedMemorySize, GEMM_SMEM);
    cudaFuncSetAttribute(gemm_mma<2>, cudaFuncAttributeMaxDynamicSharedMemorySize, GEMM_SMEM);

    // persistent grid sizing: exactly fill the chip (SMs x achievable CTAs/SM)
    int nsm = 148, occ0 = 2;
    cudaDeviceGetAttribute(&nsm, cudaDevAttrMultiProcessorCount, 0);
    cudaOccupancyMaxActiveBlocksPerMultiprocessor(&occ0, gemm_mma<0>, 256, GEMM_SMEM);
    if (occ0 < 1) occ0 = 1;
    const int pgrid = nsm * occ0;

    const int GY = (Nn + 127) / 128;         // 235 m-tiles
    const int ntWh = GY * (WH_COLS / 64);    // 1880 tiles
    const int ntRZ = GY * (512 / 64);        // 940
    const int ntN  = GY * (Hh / 64);         // 470
    const int gWh = min(pgrid, ntWh);
    const int gRZ = min(pgrid, ntRZ);
    const int gN  = min(pgrid, ntN);

    // init h + weight prep
    init_h_k<<<(Nn * Hh + 255) / 256, 256>>>(feat, hA, hA_hi, hA_lo);
    split_k<<<(WH_COLS * Hh + 255) / 256, 256>>>(W_msg, Wm_hi, Wm_lo, WH_COLS * Hh);
    prep_rz_k<<<(512 * 512 + 255) / 256, 256>>>(w_ih, w_hh, b_ih, b_hh, wrz_hi, wrz_lo, brz);
    prep_n_k<<<(256 * 256 + 255) / 256, 256>>>(w_ih, win_hi, win_lo);
    prep_n_k<<<(256 * 256 + 255) / 256, 256>>>(w_hh, whn_hi, whn_lo);

    // CSR by dst
    zero_i<<<(Nn + 255) / 256, 256>>>(cnt, Nn);
    hist_k<<<(Ee + 255) / 256, 256>>>(dst, cnt);
    scan_k<<<1, 1024>>>(cnt, rowptr);
    copy_rowptr_k<<<(Nn + 255) / 256, 256>>>(rowptr, cursor);
    scatter_k<<<(Ee + 255) / 256, 256>>>(src, dst, etype, cursor, eoff);

    float* hc = hA;       float* hn = hB;
    __nv_bfloat16 *hc_hi = hA_hi, *hc_lo = hA_lo, *hn_hi = hB_hi, *hn_lo = hB_lo;

    for (int step = 0; step < STEPS; step++) {
        const bool f16wh = (step == 1 || step == 2);  // middle steps: minimax error choice
        if (f16wh) {
            // Wh = h @ W_msg^T + b_msg -> fp16 (61 MB, L2-resident gather)
            gemm_mma<2><<<gWh, 256, GEMM_SMEM>>>(hc_hi, hc_lo, hc_hi, hc_lo, Wm_hi, Wm_lo,
                                                 b_msg, nullptr, Wh16, nullptr, nullptr, nullptr,
                                                 nullptr, nullptr, nullptr,
                                                 Nn, WH_COLS, 256, 256, 256, ntWh, WH_COLS / 64);
            aggregate_h_k<<<Nn, 64>>>(Wh16, rowptr, eoff, a_hi, a_lo);
        } else {
            // Wh = h @ W_msg^T + b_msg -> fp32 (exact)
            gemm_mma<0><<<gWh, 256, GEMM_SMEM>>>(hc_hi, hc_lo, hc_hi, hc_lo, Wm_hi, Wm_lo,
                                                 b_msg, Whf, nullptr, nullptr, nullptr, nullptr,
                                                 nullptr, nullptr, nullptr,
                                                 Nn, WH_COLS, 256, 256, 256, ntWh, WH_COLS / 64);
            aggregate_f_k<<<Nn, 64>>>(Whf, rowptr, eoff, a_hi, a_lo);
        }
        // grz = [a,h] @ w_rz^T + (b_ih+b_hh)_rz   [N, 512]
        gemm_mma<0><<<gRZ, 256, GEMM_SMEM>>>(a_hi, a_lo, hc_hi, hc_lo, wrz_hi, wrz_lo,
                                             brz, grz, nullptr, nullptr, nullptr, nullptr,
                                             nullptr, nullptr, nullptr,
                                             Nn, 512, 512, 256, 512, ntRZ, 512 / 64);
        // gin = a @ w_ih_n^T + b_ih_n   [N, 256]
        gemm_mma<0><<<gN, 256, GEMM_SMEM>>>(a_hi, a_lo, a_hi, a_lo, win_hi, win_lo,
                                            b_ih + 512, gin, nullptr, nullptr, nullptr, nullptr,
                                            nullptr, nullptr, nullptr,
                                            Nn, 256, 256, 256, 256, ntN, Hh / 64);
        // h_n GEMM + fused GRU epilogue -> h_next (+ hi/lo)
        gemm_mma<1><<<gN, 256, GEMM_SMEM>>>(hc_hi, hc_lo, hc_hi, hc_lo, whn_hi, whn_lo,
                                            b_hh + 512, nullptr, nullptr, grz, gin, hc, hn,
                                            hn_hi, hn_lo,
                                            Nn, 256, 256, 256, 256, ntN, Hh / 64);
        // swap
        float* tf = hc; hc = hn; hn = tf;
        __nv_bfloat16* tb;
        tb = hc_hi; hc_hi = hn_hi; hn_hi = tb;
        tb = hc_lo; hc_lo = hn_lo; hn_lo = tb;
    }

    // ELU + BN (training-mode batch stats)
    zero_f<<<2, 256>>>(colsum, Hh);
    zero_f<<<2, 256>>>(colsq, Hh);
    elu_stats_k<<<120, 256>>>(hc, h2, colsum, colsq);
    bn_final_k<<<1, 256>>>(colsum, colsq, bn_g, bn_b, scale, shift);
    bn_gate_k<<<(Nn + 7) / 8, 256>>>(h2, scale, shift, gate_w, gate_b, gate);

    // per-graph softmax pooling
    zero_i<<<1, 64>>>(gcnt, Gg);
    ghist_k<<<(Nn + 255) / 256, 256>>>(n2g, gcnt);
    gscan_k<<<1, 32>>>(gcnt, gstart);
    pool_k<<<Gg, 256>>>(h2, gate, gstart, alpha, hg);

    // classifier
    mlp_k<<<Gg, 128>>>(hg, W1, b1, W2, b2, out);
}

// round 17
// speedup vs baseline: 1.0942x; 1.0942x over previous
#include <cuda_runtime.h>
#include <cuda_bf16.h>
#include <cuda_fp16.h>
#include <stdint.h>
#include <math.h>

#define Nn 30000
#define Ee 480000
#define Hh 256
#define Tt 4
#define Gg 64
#define Cc 10
#define STEPS 5
#define BN_EPS 1e-5f

#define WH_COLS (Tt * Hh)      // 1024

// ---------------- scratch (device globals; no runtime allocation) ----------------
__device__ float g_hA[Nn * Hh];
__device__ float g_hB[Nn * Hh];
__device__ float  g_Whf[Nn * WH_COLS];   // fp32 message matrix (steps 0,3,4)
__device__ __half g_Wh16[Nn * WH_COLS];  // fp16 message matrix (steps 1,2; L2-resident)
__device__ float g_grz[Nn * 512];
__device__ float g_gin[Nn * Hh];
__device__ float g_h2[Nn * Hh];
__device__ float g_gate[Nn];
__device__ float g_alpha[Nn];
__device__ float g_hg[Gg * Hh];
__device__ float g_colsum[Hh];
__device__ float g_colsq[Hh];
__device__ float g_scale[Hh];
__device__ float g_shift[Hh];
__device__ float g_bias_rz[512];
__device__ int   g_cnt[Nn];
__device__ int   g_rowptr[Nn + 1];
__device__ int   g_cursor[Nn];
__device__ int   g_eoff[Ee];
__device__ int   g_gcnt[Gg];
__device__ int   g_gstart[Gg + 1];
// bf16 hi/lo split operands for tensor-core GEMMs
__device__ __nv_bfloat16 g_hA_hi[Nn * Hh];
__device__ __nv_bfloat16 g_hA_lo[Nn * Hh];
__device__ __nv_bfloat16 g_hB_hi[Nn * Hh];
__device__ __nv_bfloat16 g_hB_lo[Nn * Hh];
__device__ __nv_bfloat16 g_a_hi[Nn * Hh];
__device__ __nv_bfloat16 g_a_lo[Nn * Hh];
__device__ __nv_bfloat16 g_Wm_hi[WH_COLS * Hh];
__device__ __nv_bfloat16 g_Wm_lo[WH_COLS * Hh];
__device__ __nv_bfloat16 g_wrz_hi[512 * 512];   // [512 out rows][K=512: w_ih | w_hh]
__device__ __nv_bfloat16 g_wrz_lo[512 * 512];
__device__ __nv_bfloat16 g_win_hi[Hh * Hh];     // w_ih rows 512:768
__device__ __nv_bfloat16 g_win_lo[Hh * Hh];
__device__ __nv_bfloat16 g_whn_hi[Hh * Hh];     // w_hh rows 512:768
__device__ __nv_bfloat16 g_whn_lo[Hh * Hh];

// ---------------- ptx helpers (baseline ISA) ----------------
__device__ __forceinline__ uint32_t smem_u32(const void* p) {
    uint32_t a;
    asm("{ .reg .u64 t; cvta.to.shared.u64 t, %1; cvt.u32.u64 %0, t; }" : "=r"(a) : "l"(p));
    return a;
}
__device__ __forceinline__ void ldm_x4(uint32_t& r0, uint32_t& r1, uint32_t& r2, uint32_t& r3,
                                       uint32_t addr) {
    asm volatile("ldmatrix.sync.aligned.m8n8.x4.shared.b16 {%0,%1,%2,%3}, [%4];"
                 : "=r"(r0), "=r"(r1), "=r"(r2), "=r"(r3) : "r"(addr));
}
__device__ __forceinline__ void mma_bf16(float* d, const uint32_t* a, const uint32_t* b) {
    asm volatile(
        "mma.sync.aligned.m16n8k16.row.col.f32.bf16.bf16.f32 "
        "{%0,%1,%2,%3}, {%4,%5,%6,%7}, {%8,%9}, {%0,%1,%2,%3};"
        : "+f"(d[0]), "+f"(d[1]), "+f"(d[2]), "+f"(d[3])
        : "r"(a[0]), "r"(a[1]), "r"(a[2]), "r"(a[3]), "r"(b[0]), "r"(b[1]));
}
__device__ __forceinline__ void cp16(uint32_t saddr, const void* gaddr) {
    asm volatile("cp.async.cg.shared.global [%0], [%1], 16;" :: "r"(saddr), "l"(gaddr));
}
#define CP_COMMIT() asm volatile("cp.async.commit_group;")
#define CP_WAIT1()  asm volatile("cp.async.wait_group 1;")

// ---------------- tensor-core GEMM via mma.sync, cp.async double-buffered ------------
// C[M,Ncols] = (A||A2)[M,Kloop] @ (Bhi+Blo)[Ncols,Kloop]^T  (+ epilogue)
// A row stride is always 256. K chunks >= kSplit read A2 at k-kSplit.
// fp32 emulation: C = Ahi*Bhi + Ahi*Blo + Alo*Bhi
// BM=128, BN=64, BK=32, 8 warps (4x2), warp tile 32x32, 2 smem stages.
// MODE 0: C(fp32) = acc + bias[col]
// MODE 1: fused GRU epilogue: acc = h@w_hh_n^T; uses grz, gin, hold; writes hnew + bf16 hi/lo
// MODE 2: Ch(fp16) = acc + bias[col]   (message matrix, fp16 steps)
#define SSTR 40  // smem row stride in bf16 elems (80 B, 16B-aligned for ldmatrix)
#define OFF_ALO 10240
#define OFF_BHI 20480
#define OFF_BLO 25600
#define STAGE_BYTES 30720
#define GEMM_SMEM (2 * STAGE_BYTES)

template <int MODE>
__global__ __launch_bounds__(256) void gemm_mma(
    const __nv_bfloat16* __restrict__ Ahi, const __nv_bfloat16* __restrict__ Alo,
    const __nv_bfloat16* __restrict__ A2hi, const __nv_bfloat16* __restrict__ A2lo,
    const __nv_bfloat16* __restrict__ Bhi, const __nv_bfloat16* __restrict__ Blo,
    const float* __restrict__ bias, float* __restrict__ C, __half* __restrict__ Ch,
    const float* __restrict__ grz, const float* __restrict__ gin,
    const float* __restrict__ hold, float* __restrict__ hnew,
    __nv_bfloat16* __restrict__ hnhi, __nv_bfloat16* __restrict__ hnlo,
    int M, int Ncols, int Kloop, int kSplit, int ldb) {
    extern __shared__ char smem[];
    const uint32_t sbase = smem_u32(smem);

    const int tid = threadIdx.x;
    const int warp = tid >> 5;
    const int lane = tid & 31;
    const int wm = warp >> 1;
    const int wn = warp & 1;
    const int m0 = blockIdx.y * 128;
    const int n0 = blockIdx.x * 64;

    const int grow = tid >> 2;
    const int gk4 = (tid & 3) * 8;
    const int arow0 = min(m0 + grow, M - 1);   // clamp (row m affects only C row m)
    const int arow1 = min(m0 + grow + 64, M - 1);
    const int brow = n0 + grow;
    const uint32_t sA0 = (uint32_t)((grow * SSTR + gk4) * 2);
    const uint32_t sA1 = (uint32_t)(((grow + 64) * SSTR + gk4) * 2);
    const uint32_t sB0 = (uint32_t)((grow * SSTR + gk4) * 2);

    const int alr = lane & 15, alh = lane >> 4;
    uint32_t aoff[2];
#pragma unroll
    for (int tm = 0; tm < 2; tm++)
        aoff[tm] = (uint32_t)((wm * 32 + tm * 16 + alr) * (SSTR * 2) + alh * 16);
    const int bnr = (lane & 7) + ((lane >> 4) & 1) * 8;
    const int bkh = ((lane >> 3) & 1) * 16;
    uint32_t boff[2];
#pragma unroll
    for (int bt = 0; bt < 2; bt++)
        boff[bt] = (uint32_t)((wn * 32 + bt * 16 + bnr) * (SSTR * 2) + bkh);

    float acc[2][4][4];
#pragma unroll
    for (int i = 0; i < 2; i++)
#pragma unroll
        for (int j = 0; j < 4; j++)
#pragma unroll
            for (int q = 0; q < 4; q++) acc[i][j][q] = 0.0f;

#define ISSUE_LOADS(K0, S)                                                             \
    do {                                                                               \
        uint32_t b_ = sbase + (S) * STAGE_BYTES;                                       \
        const bool sec_ = (K0) >= kSplit;                                              \
        const __nv_bfloat16* pAhi_ = sec_ ? A2hi : Ahi;                                \
        const __nv_bfloat16* pAlo_ = sec_ ? A2lo : Alo;                                \
        const int ko_ = sec_ ? (K0) - kSplit : (K0);                                   \
        cp16(b_ + sA0, pAhi_ + (size_t)arow0 * 256 + ko_ + gk4);                       \
        cp16(b_ + sA1, pAhi_ + (size_t)arow1 * 256 + ko_ + gk4);                       \
        cp16(b_ + OFF_ALO + sA0, pAlo_ + (size_t)arow0 * 256 + ko_ + gk4);             \
        cp16(b_ + OFF_ALO + sA1, pAlo_ + (size_t)arow1 * 256 + ko_ + gk4);             \
        cp16(b_ + OFF_BHI + sB0, Bhi + (size_t)brow * ldb + (K0) + gk4);               \
        cp16(b_ + OFF_BLO + sB0, Blo + (size_t)brow * ldb + (K0) + gk4);               \
    } while (0)

    const int niter = Kloop >> 5;
    ISSUE_LOADS(0, 0);
    CP_COMMIT();

    for (int it = 0; it < niter; it++) {
        if (it + 1 < niter) ISSUE_LOADS((it + 1) * 32, (it + 1) & 1);
        CP_COMMIT();
        CP_WAIT1();
        __syncthreads();

        const uint32_t stg = sbase + (it & 1) * STAGE_BYTES;
#pragma unroll
        for (int kk = 0; kk < 2; kk++) {
            uint32_t ah[2][4], al[2][4], bh[2][4], bl[2][4];
#pragma unroll
            for (int tm = 0; tm < 2; tm++) {
                ldm_x4(ah[tm][0], ah[tm][1], ah[tm][2], ah[tm][3], stg + aoff[tm] + kk * 32);
                ldm_x4(al[tm][0], al[tm][1], al[tm][2], al[tm][3], stg + OFF_ALO + aoff[tm] + kk * 32);
            }
#pragma unroll
            for (int bt = 0; bt < 2; bt++) {
                ldm_x4(bh[bt][0], bh[bt][1], bh[bt][2], bh[bt][3], stg + OFF_BHI + boff[bt] + kk * 32);
                ldm_x4(bl[bt][0], bl[bt][1], bl[bt][2], bl[bt][3], stg + OFF_BLO + boff[bt] + kk * 32);
            }
#pragma unroll
            for (int tm = 0; tm < 2; tm++) {
#pragma unroll
                for (int tn = 0; tn < 4; tn++) {
                    const uint32_t* bph = &bh[tn >> 1][(tn & 1) * 2];
                    const uint32_t* bpl = &bl[tn >> 1][(tn & 1) * 2];
                    mma_bf16(acc[tm][tn], ah[tm], bph);
                    mma_bf16(acc[tm][tn], ah[tm], bpl);
                    mma_bf16(acc[tm][tn], al[tm], bph);
                }
            }
        }
        __syncthreads();
    }

    const int erow = (lane >> 2);
    const int ecol = (lane & 3) * 2;
#pragma unroll
    for (int tm = 0; tm < 2; tm++) {
#pragma unroll
        for (int tn = 0; tn < 4; tn++) {
            int col = n0 + wn * 32 + tn * 8 + ecol;
            float2 bv = *(const float2*)&bias[col];
#pragma unroll
            for (int half = 0; half < 2; half++) {
                int r = m0 + wm * 32 + tm * 16 + erow + half * 8;
                if (r >= M) continue;
                float vx = acc[tm][tn][half * 2 + 0] + bv.x;
                float vy = acc[tm][tn][half * 2 + 1] + bv.y;
                if (MODE == 0) {
                    float2 o;
                    o.x = vx;
                    o.y = vy;
                    *(float2*)&C[(size_t)r * Ncols + col] = o;
                } else if (MODE == 2) {
                    __half2 o;
                    o.x = __float2half(vx);
                    o.y = __float2half(vy);
                    *(__half2*)&Ch[(size_t)r * Ncols + col] = o;
                } else {
                    float2 rz_r = *(const float2*)&grz[(size_t)r * 512 + col];
                    float2 rz_z = *(const float2*)&grz[(size_t)r * 512 + 256 + col];
                    float2 gn = *(const float2*)&gin[(size_t)r * 256 + col];
                    float2 ho = *(const float2*)&hold[(size_t)r * 256 + col];
                    float rr0 = 1.0f / (1.0f + expf(-rz_r.x));
                    float rr1 = 1.0f / (1.0f + expf(-rz_r.y));
                    float zz0 = 1.0f / (1.0f + expf(-rz_z.x));
                    float zz1 = 1.0f / (1.0f + expf(-rz_z.y));
                    float nn0 = tanhf(gn.x + rr0 * vx);
                    float nn1 = tanhf(gn.y + rr1 * vy);
                    float o0 = (1.0f - zz0) * nn0 + zz0 * ho.x;
                    float o1 = (1.0f - zz1) * nn1 + zz1 * ho.y;
                    float2 ov;
                    ov.x = o0;
                    ov.y = o1;
                    *(float2*)&hnew[(size_t)r * 256 + col] = ov;
                    __nv_bfloat16 h0 = __float2bfloat16(o0);
                    __nv_bfloat16 h1 = __float2bfloat16(o1);
                    __nv_bfloat162 hv, lv;
                    hv.x = h0;
                    hv.y = h1;
                    lv.x = __float2bfloat16(o0 - __bfloat162float(h0));
                    lv.y = __float2bfloat16(o1 - __bfloat162float(h1));
                    *(__nv_bfloat162*)&hnhi[(size_t)r * 256 + col] = hv;
                    *(__nv_bfloat162*)&hnlo[(size_t)r * 256 + col] = lv;
                }
            }
        }
    }
}

// ---------------- weight prep ----------------
__global__ void split_k(const float* __restrict__ x, __nv_bfloat16* __restrict__ hi,
                        __nv_bfloat16* __restrict__ lo, int n) {
    int i = blockIdx.x * blockDim.x + threadIdx.x;
    if (i < n) {
        float v = x[i];
        __nv_bfloat16 h = __float2bfloat16(v);
        hi[i] = h;
        lo[i] = __float2bfloat16(v - __bfloat162float(h));
    }
}
__global__ void prep_rz_k(const float* __restrict__ wih, const float* __restrict__ whh,
                          const float* __restrict__ bih, const float* __restrict__ bhh,
                          __nv_bfloat16* __restrict__ hi, __nv_bfloat16* __restrict__ lo,
                          float* __restrict__ brz) {
    int i = blockIdx.x * blockDim.x + threadIdx.x;
    if (i >= 512 * 512) return;
    int j = i >> 9;
    int k = i & 511;
    float v = (k < 256) ? wih[j * 256 + k] : whh[j * 256 + (k - 256)];
    __nv_bfloat16 h = __float2bfloat16(v);
    hi[i] = h;
    lo[i] = __float2bfloat16(v - __bfloat162float(h));
    if (i < 512) brz[i] = bih[i] + bhh[i];
}
__global__ void prep_n_k(const float* __restrict__ w, __nv_bfloat16* __restrict__ hi,
                         __nv_bfloat16* __restrict__ lo) {
    int i = blockIdx.x * blockDim.x + threadIdx.x;
    if (i >= 256 * 256) return;
    float v = w[512 * 256 + i];
    __nv_bfloat16 h = __float2bfloat16(v);
    hi[i] = h;
    lo[i] = __float2bfloat16(v - __bfloat162float(h));
}
__global__ void init_h_k(const float* __restrict__ feat, float* __restrict__ h,
                         __nv_bfloat16* __restrict__ hhi, __nv_bfloat16* __restrict__ hlo) {
    int i = blockIdx.x * blockDim.x + threadIdx.x;
    if (i < Nn * Hh) {
        float v = feat[i];
        h[i] = v;
        __nv_bfloat16 hb = __float2bfloat16(v);
        hhi[i] = hb;
        hlo[i] = __float2bfloat16(v - __bfloat162float(hb));
    }
}

// ---------------- CSR construction ----------------
__global__ void zero_f(float* p, int n) {
    int i = blockIdx.x * blockDim.x + threadIdx.x;
    if (i < n) p[i] = 0.0f;
}
__global__ void zero_i(int* p, int n) {
    int i = blockIdx.x * blockDim.x + threadIdx.x;
    if (i < n) p[i] = 0;
}
__global__ void hist_k(const int* __restrict__ dst, int* cnt) {
    int e = blockIdx.x * blockDim.x + threadIdx.x;
    if (e < Ee) atomicAdd(&cnt[dst[e]], 1);
}
__global__ void scan_k(const int* __restrict__ cnt, int* rowptr) {
    __shared__ int partial[1024];
    const int CH = (Nn + 1023) / 1024;
    int tid = threadIdx.x;
    int base = tid * CH;
    int s = 0;
#pragma unroll
    for (int i = 0; i < CH; i++) {
        int idx = base + i;
        if (idx < Nn) s += cnt[idx];
    }
    partial[tid] = s;
    __syncthreads();
    for (int off = 1; off < 1024; off <<= 1) {
        int v = (tid >= off) ? partial[tid - off] : 0;
        __syncthreads();
        partial[tid] += v;
        __syncthreads();
    }
    int run = partial[tid] - s;
    for (int i = 0; i < CH; i++) {
        int idx = base + i;
        if (idx < Nn) { rowptr[idx] = run; run += cnt[idx]; }
    }
    if (tid == 1023) rowptr[Nn] = partial[1023];
}
__global__ void copy_rowptr_k(const int* __restrict__ rowptr, int* cursor) {
    int i = blockIdx.x * blockDim.x + threadIdx.x;
    if (i < Nn) cursor[i] = rowptr[i];
}
__global__ void scatter_k(const int* __restrict__ src, const int* __restrict__ dst,
                          const int* __restrict__ etype, int* cursor, int* eoff) {
    int e = blockIdx.x * blockDim.x + threadIdx.x;
    if (e < Ee) {
        int pos = atomicAdd(&cursor[dst[e]], 1);
        eoff[pos] = src[e] * WH_COLS + etype[e] * Hh;
    }
}

// ---------------- edge aggregation (fp32 Wh): a[d] = sum Wh[etype,src] ----------------
__global__ void aggregate_f_k(const float* __restrict__ Wh, const int* __restrict__ rowptr,
                              const int* __restrict__ eoff,
                              __nv_bfloat16* __restrict__ ahi, __nv_bfloat16* __restrict__ alo) {
    int d = blockIdx.x;
    int lane = threadIdx.x;  // 64 threads, 4 floats each
    int s = rowptr[d];
    int e = rowptr[d + 1];
    float4 acc0 = make_float4(0.f, 0.f, 0.f, 0.f);
    float4 acc1 = make_float4(0.f, 0.f, 0.f, 0.f);
    int i = s;
    for (; i + 1 < e; i += 2) {
        int o0 = __ldg(&eoff[i]);
        int o1 = __ldg(&eoff[i + 1]);
        float4 v0 = __ldg((const float4*)&Wh[o0] + lane);
        float4 v1 = __ldg((const float4*)&Wh[o1] + lane);
        acc0.x += v0.x; acc0.y += v0.y; acc0.z += v0.z; acc0.w += v0.w;
        acc1.x += v1.x; acc1.y += v1.y; acc1.z += v1.z; acc1.w += v1.w;
    }
    if (i < e) {
        int o0 = __ldg(&eoff[i]);
        float4 v0 = __ldg((const float4*)&Wh[o0] + lane);
        acc0.x += v0.x; acc0.y += v0.y; acc0.z += v0.z; acc0.w += v0.w;
    }
    float vals[4] = {acc0.x + acc1.x, acc0.y + acc1.y, acc0.z + acc1.z, acc0.w + acc1.w};
    __nv_bfloat16 hb[4], lb[4];
#pragma unroll
    for (int q = 0; q < 4; q++) {
        hb[q] = __float2bfloat16(vals[q]);
        lb[q] = __float2bfloat16(vals[q] - __bfloat162float(hb[q]));
    }
    *(uint2*)&ahi[(size_t)d * Hh + lane * 4] = *(uint2*)hb;
    *(uint2*)&alo[(size_t)d * Hh + lane * 4] = *(uint2*)lb;
}

// ---------------- edge aggregation (fp16 Wh, L2-resident): fp32 accumulation ----------------
__global__ void aggregate_h_k(const __half* __restrict__ Wh, const int* __restrict__ rowptr,
                              const int* __restrict__ eoff,
                              __nv_bfloat16* __restrict__ ahi, __nv_bfloat16* __restrict__ alo) {
    int d = blockIdx.x;
    int lane = threadIdx.x;  // 64 threads, 4 halves each
    int s = rowptr[d];
    int e = rowptr[d + 1];
    float4 acc0 = make_float4(0.f, 0.f, 0.f, 0.f);
    float4 acc1 = make_float4(0.f, 0.f, 0.f, 0.f);
    int i = s;
    for (; i + 1 < e; i += 2) {
        int o0 = __ldg(&eoff[i]);
        int o1 = __ldg(&eoff[i + 1]);
        uint2 u0 = __ldg((const uint2*)&Wh[o0] + lane);
        uint2 u1 = __ldg((const uint2*)&Wh[o1] + lane);
        float2 f00 = __half22float2(*(__half2*)&u0.x);
        float2 f01 = __half22float2(*(__half2*)&u0.y);
        float2 f10 = __half22float2(*(__half2*)&u1.x);
        float2 f11 = __half22float2(*(__half2*)&u1.y);
        acc0.x += f00.x; acc0.y += f00.y; acc0.z += f01.x; acc0.w += f01.y;
        acc1.x += f10.x; acc1.y += f10.y; acc1.z += f11.x; acc1.w += f11.y;
    }
    if (i < e) {
        int o0 = __ldg(&eoff[i]);
        uint2 u0 = __ldg((const uint2*)&Wh[o0] + lane);
        float2 f00 = __half22float2(*(__half2*)&u0.x);
        float2 f01 = __half22float2(*(__half2*)&u0.y);
        acc0.x += f00.x; acc0.y += f00.y; acc0.z += f01.x; acc0.w += f01.y;
    }
    float vals[4] = {acc0.x + acc1.x, acc0.y + acc1.y, acc0.z + acc1.z, acc0.w + acc1.w};
    __nv_bfloat16 hb[4], lb[4];
#pragma unroll
    for (int q = 0; q < 4; q++) {
        hb[q] = __float2bfloat16(vals[q]);
        lb[q] = __float2bfloat16(vals[q] - __bfloat162float(hb[q]));
    }
    *(uint2*)&ahi[(size_t)d * Hh + lane * 4] = *(uint2*)hb;
    *(uint2*)&alo[(size_t)d * Hh + lane * 4] = *(uint2*)lb;
}

// ---------------- ELU + batchnorm stats ----------------
__global__ void elu_stats_k(const float* __restrict__ h, float* __restrict__ h2,
                            float* colsum, float* colsq) {
    int c = threadIdx.x;
    int rows_per_block = (Nn + gridDim.x - 1) / gridDim.x;
    int r0 = blockIdx.x * rows_per_block;
    int r1 = min(Nn, r0 + rows_per_block);
    float s = 0.f, q = 0.f;
    for (int r = r0; r < r1; r++) {
        float x = h[(size_t)r * Hh + c];
        float e = x > 0.f ? x : expm1f(x);
        h2[(size_t)r * Hh + c] = e;
        s += e;
        q += e * e;
    }
    atomicAdd(&colsum[c], s);
    atomicAdd(&colsq[c], q);
}
__global__ void bn_final_k(const float* __restrict__ colsum, const float* __restrict__ colsq,
                           const float* __restrict__ gamma, const float* __restrict__ beta,
                           float* scale, float* shift) {
    int c = threadIdx.x;
    float mu = colsum[c] * (1.0f / Nn);
    float var = colsq[c] * (1.0f / Nn) - mu * mu;
    float k = rsqrtf(var + BN_EPS) * gamma[c];
    scale[c] = k;
    shift[c] = beta[c] - mu * k;
}
__global__ void bn_gate_k(float* __restrict__ h2, const float* __restrict__ scale,
                          const float* __restrict__ shift, const float* __restrict__ gw,
                          const float* __restrict__ gb, float* __restrict__ gate) {
    int n = blockIdx.x * 8 + (threadIdx.x >> 5);
    int lane = threadIdx.x & 31;
    if (n >= Nn) return;
    float s = 0.f;
#pragma unroll
    for (int j = 0; j < 8; j++) {
        int c = lane + j * 32;
        float v = h2[(size_t)n * Hh + c] * scale[c] + shift[c];
        h2[(size_t)n * Hh + c] = v;
        s += v * gw[c];
    }
#pragma unroll
    for (int o = 16; o > 0; o >>= 1) s += __shfl_xor_sync(0xffffffffu, s, o);
    if (lane == 0) gate[n] = s + gb[0];
}

// ---------------- per-graph ranges + pooling + classifier ----------------
__global__ void ghist_k(const int* __restrict__ n2g, int* gcnt) {
    int i = blockIdx.x * blockDim.x + threadIdx.x;
    if (i < Nn) atomicAdd(&gcnt[n2g[i]], 1);
}
__global__ void gscan_k(const int* __restrict__ gcnt, int* gstart) {
    if (threadIdx.x == 0 && blockIdx.x == 0) {
        int r = 0;
        for (int g = 0; g < Gg; g++) { gstart[g] = r; r += gcnt[g]; }
        gstart[Gg] = r;
    }
}
__global__ void pool_k(const float* __restrict__ h2, const float* __restrict__ gate,
                       const int* __restrict__ gstart, float* __restrict__ alpha,
                       float* __restrict__ hg) {
    int g = blockIdx.x;
    int t = threadIdx.x;
    __shared__ float red[256];
    int s = gstart[g];
    int e = gstart[g + 1];
    if (e == s) { hg[g * Hh + t] = 0.0f; return; }
    float mx = -3.402823e38f;
    for (int n = s + t; n < e; n += 256) mx = fmaxf(mx, gate[n]);
    red[t] = mx;
    __syncthreads();
    for (int o = 128; o > 0; o >>= 1) {
        if (t < o) red[t] = fmaxf(red[t], red[t + o]);
        __syncthreads();
    }
    mx = red[0];
    __syncthreads();
    float sm = 0.f;
    for (int n = s + t; n < e; n += 256) {
        float ee = expf(gate[n] - mx);
        alpha[n] = ee;
        sm += ee;
    }
    red[t] = sm;
    __syncthreads();
    for (int o = 128; o > 0; o >>= 1) {
        if (t < o) red[t] += red[t + o];
        __syncthreads();
    }
    float inv = 1.0f / red[0];
    __syncthreads();
    float acc0 = 0.f, acc1 = 0.f, acc2 = 0.f, acc3 = 0.f;
    int n = s;
    for (; n + 3 < e; n += 4) {
        acc0 += alpha[n + 0] * h2[(size_t)(n + 0) * Hh + t];
        acc1 += alpha[n + 1] * h2[(size_t)(n + 1) * Hh + t];
        acc2 += alpha[n + 2] * h2[(size_t)(n + 2) * Hh + t];
        acc3 += alpha[n + 3] * h2[(size_t)(n + 3) * Hh + t];
    }
    for (; n < e; n++) acc0 += alpha[n] * h2[(size_t)n * Hh + t];
    hg[g * Hh + t] = (acc0 + acc1 + acc2 + acc3) * inv;
}
__global__ void mlp_k(const float* __restrict__ hg, const float* __restrict__ W1,
                      const float* __restrict__ b1, const float* __restrict__ W2,
                      const float* __restrict__ b2, float* __restrict__ out) {
    int g = blockIdx.x;
    int t = threadIdx.x;
    __shared__ float sh[256];
    __shared__ float sx[128];
    sh[t] = hg[g * Hh + t];
    sh[t + 128] = hg[g * Hh + t + 128];
    __syncthreads();
    float s = b1[t];
#pragma unroll 8
    for (int j = 0; j < 256; j++) s += sh[j] * W1[t * 256 + j];
    sx[t] = fmaxf(s, 0.f);
    __syncthreads();
    if (t < Cc) {
        float o = b2[t];
#pragma unroll 8
        for (int j = 0; j < 128; j++) o += sx[j] * W2[t * 128 + j];
        out[g * Cc + t] = o;
    }
}

// ---------------- launcher ----------------
extern "C" void kernel_launch(void* const* d_in, const int* in_sizes, int n_in,
                              void* d_out, int out_size) {
    const float* feat   = (const float*)d_in[0];
    const int*   src    = (const int*)d_in[1];
    const int*   dst    = (const int*)d_in[2];
    const int*   etype  = (const int*)d_in[3];
    const int*   n2g    = (const int*)d_in[4];
    const float* W_msg  = (const float*)d_in[5];
    const float* b_msg  = (const float*)d_in[6];
    const float* w_ih   = (const float*)d_in[7];
    const float* w_hh   = (const float*)d_in[8];
    const float* b_ih   = (const float*)d_in[9];
    const float* b_hh   = (const float*)d_in[10];
    const float* bn_g   = (const float*)d_in[11];
    const float* bn_b   = (const float*)d_in[12];
    const float* gate_w = (const float*)d_in[13];
    const float* gate_b = (const float*)d_in[14];
    const float* W1     = (const float*)d_in[15];
    const float* b1     = (const float*)d_in[16];
    const float* W2     = (const float*)d_in[17];
    const float* b2     = (const float*)d_in[18];
    float* out = (float*)d_out;

    float *hA, *hB, *Whf, *grz, *gin, *h2, *gate, *alpha, *hg, *colsum, *colsq, *scale, *shift, *brz;
    __half* Wh16;
    int *cnt, *rowptr, *cursor, *eoff, *gcnt, *gstart;
    __nv_bfloat16 *hA_hi, *hA_lo, *hB_hi, *hB_lo, *a_hi, *a_lo;
    __nv_bfloat16 *Wm_hi, *Wm_lo, *wrz_hi, *wrz_lo, *win_hi, *win_lo, *whn_hi, *whn_lo;
    cudaGetSymbolAddress((void**)&hA, g_hA);
    cudaGetSymbolAddress((void**)&hB, g_hB);
    cudaGetSymbolAddress((void**)&Whf, g_Whf);
    cudaGetSymbolAddress((void**)&Wh16, g_Wh16);
    cudaGetSymbolAddress((void**)&grz, g_grz);
    cudaGetSymbolAddress((void**)&gin, g_gin);
    cudaGetSymbolAddress((void**)&h2, g_h2);
    cudaGetSymbolAddress((void**)&gate, g_gate);
    cudaGetSymbolAddress((void**)&alpha, g_alpha);
    cudaGetSymbolAddress((void**)&hg, g_hg);
    cudaGetSymbolAddress((void**)&colsum, g_colsum);
    cudaGetSymbolAddress((void**)&colsq, g_colsq);
    cudaGetSymbolAddress((void**)&scale, g_scale);
    cudaGetSymbolAddress((void**)&shift, g_shift);
    cudaGetSymbolAddress((void**)&brz, g_bias_rz);
    cudaGetSymbolAddress((void**)&cnt, g_cnt);
    cudaGetSymbolAddress((void**)&rowptr, g_rowptr);
    cudaGetSymbolAddress((void**)&cursor, g_cursor);
    cudaGetSymbolAddress((void**)&eoff, g_eoff);
    cudaGetSymbolAddress((void**)&gcnt, g_gcnt);
    cudaGetSymbolAddress((void**)&gstart, g_gstart);
    cudaGetSymbolAddress((void**)&hA_hi, g_hA_hi);
    cudaGetSymbolAddress((void**)&hA_lo, g_hA_lo);
    cudaGetSymbolAddress((void**)&hB_hi, g_hB_hi);
    cudaGetSymbolAddress((void**)&hB_lo, g_hB_lo);
    cudaGetSymbolAddress((void**)&a_hi, g_a_hi);
    cudaGetSymbolAddress((void**)&a_lo, g_a_lo);
    cudaGetSymbolAddress((void**)&Wm_hi, g_Wm_hi);
    cudaGetSymbolAddress((void**)&Wm_lo, g_Wm_lo);
    cudaGetSymbolAddress((void**)&wrz_hi, g_wrz_hi);
    cudaGetSymbolAddress((void**)&wrz_lo, g_wrz_lo);
    cudaGetSymbolAddress((void**)&win_hi, g_win_hi);
    cudaGetSymbolAddress((void**)&win_lo, g_win_lo);
    cudaGetSymbolAddress((void**)&whn_hi, g_whn_hi);
    cudaGetSymbolAddress((void**)&whn_lo, g_whn_lo);

    cudaFuncSetAttribute(gemm_mma<0>, cudaFuncAttributeMaxDynamicSharedMemorySize, GEMM_SMEM);
    cudaFuncSetAttribute(gemm_mma<1>, cudaFuncAttributeMaxDynamicSharedMemorySize, GEMM_SMEM);
    cudaFuncSetAttribute(gemm_mma<2>, cudaFuncAttributeMaxDynamicSharedMemorySize, GEMM_SMEM);

    // init h + weight prep
    init_h_k<<<(Nn * Hh + 255) / 256, 256>>>(feat, hA, hA_hi, hA_lo);
    split_k<<<(WH_COLS * Hh + 255) / 256, 256>>>(W_msg, Wm_hi, Wm_lo, WH_COLS * Hh);
    prep_rz_k<<<(512 * 512 + 255) / 256, 256>>>(w_ih, w_hh, b_ih, b_hh, wrz_hi, wrz_lo, brz);
    prep_n_k<<<(256 * 256 + 255) / 256, 256>>>(w_ih, win_hi, win_lo);
    prep_n_k<<<(256 * 256 + 255) / 256, 256>>>(w_hh, whn_hi, whn_lo);

    // CSR by dst
    zero_i<<<(Nn + 255) / 256, 256>>>(cnt, Nn);
    hist_k<<<(Ee + 255) / 256, 256>>>(dst, cnt);
    scan_k<<<1, 1024>>>(cnt, rowptr);
    copy_rowptr_k<<<(Nn + 255) / 256, 256>>>(rowptr, cursor);
    scatter_k<<<(Ee + 255) / 256, 256>>>(src, dst, etype, cursor, eoff);

    dim3 gridWh(WH_COLS / 64, (Nn + 127) / 128);
    dim3 gridRZ(512 / 64, (Nn + 127) / 128);
    dim3 gridN(Hh / 64, (Nn + 127) / 128);

    float* hc = hA;       float* hn = hB;
    __nv_bfloat16 *hc_hi = hA_hi, *hc_lo = hA_lo, *hn_hi = hB_hi, *hn_lo = hB_lo;

    for (int step = 0; step < STEPS; step++) {
        const bool f16wh = (step == 1 || step == 2);  // middle steps: minimax error choice
        if (f16wh) {
            // Wh = h @ W_msg^T + b_msg -> fp16 (61 MB, L2-resident gather)
            gemm_mma<2><<<gridWh, 256, GEMM_SMEM>>>(hc_hi, hc_lo, hc_hi, hc_lo, Wm_hi, Wm_lo,
                                                    b_msg, nullptr, Wh16, nullptr, nullptr, nullptr,
                                                    nullptr, nullptr, nullptr, Nn, WH_COLS, 256, 256, 256);
            aggregate_h_k<<<Nn, 64>>>(Wh16, rowptr, eoff, a_hi, a_lo);
        } else {
            // Wh = h @ W_msg^T + b_msg -> fp32 (exact)
            gemm_mma<0><<<gridWh, 256, GEMM_SMEM>>>(hc_hi, hc_lo, hc_hi, hc_lo, Wm_hi, Wm_lo,
                                                    b_msg, Whf, nullptr, nullptr, nullptr, nullptr,
                                                    nullptr, nullptr, nullptr, Nn, WH_COLS, 256, 256, 256);
            aggregate_f_k<<<Nn, 64>>>(Whf, rowptr, eoff, a_hi, a_lo);
        }
        // grz = [a,h] @ w_rz^T + (b_ih+b_hh)_rz   [N, 512]
        gemm_mma<0><<<gridRZ, 256, GEMM_SMEM>>>(a_hi, a_lo, hc_hi, hc_lo, wrz_hi, wrz_lo,
                                                brz, grz, nullptr, nullptr, nullptr, nullptr,
                                                nullptr, nullptr, nullptr, Nn, 512, 512, 256, 512);
        // gin = a @ w_ih_n^T + b_ih_n   [N, 256]
        gemm_mma<0><<<gridN, 256, GEMM_SMEM>>>(a_hi, a_lo, a_hi, a_lo, win_hi, win_lo,
                                               b_ih + 512, gin, nullptr, nullptr, nullptr, nullptr,
                                               nullptr, nullptr, nullptr, Nn, 256, 256, 256, 256);
        // h_n GEMM + fused GRU epilogue -> h_next (+ hi/lo)
        gemm_mma<1><<<gridN, 256, GEMM_SMEM>>>(hc_hi, hc_lo, hc_hi, hc_lo, whn_hi, whn_lo,
                                               b_hh + 512, nullptr, nullptr, grz, gin, hc, hn,
                                               hn_hi, hn_lo, Nn, 256, 256, 256, 256);
        // swap
        float* tf = hc; hc = hn; hn = tf;
        __nv_bfloat16* tb;
        tb = hc_hi; hc_hi = hn_hi; hn_hi = tb;
        tb = hc_lo; hc_lo = hn_lo; hn_lo = tb;
    }

    // ELU + BN (training-mode batch stats)
    zero_f<<<2, 256>>>(colsum, Hh);
    zero_f<<<2, 256>>>(colsq, Hh);
    elu_stats_k<<<120, 256>>>(hc, h2, colsum, colsq);
    bn_final_k<<<1, 256>>>(colsum, colsq, bn_g, bn_b, scale, shift);
    bn_gate_k<<<(Nn + 7) / 8, 256>>>(h2, scale, shift, gate_w, gate_b, gate);

    // per-graph softmax pooling
    zero_i<<<1, 64>>>(gcnt, Gg);
    ghist_k<<<(Nn + 255) / 256, 256>>>(n2g, gcnt);
    gscan_k<<<1, 32>>>(gcnt, gstart);
    pool_k<<<Gg, 256>>>(h2, gate, gstart, alpha, hg);

    // classifier
    mlp_k<<<Gg, 128>>>(hg, W1, b1, W2, b2, out);
}